// round 9
// baseline (speedup 1.0000x reference)
#include <cuda_runtime.h>
#include <cuda_bf16.h>
#include <cstdint>

// ---------------- problem constants ----------------
#define BB 16
#define HH 56
#define WW 56
#define LL (HH*WW)      // 3136
#define DD 128
#define KK 4
#define NSEG 112
#define SEGLEN 28       // 112*28 = 3136

#define LOG2E 1.4426950408889634f
#define LN2   0.6931471805599453f

// ---------------- scratch (device globals; no allocs allowed) ----------------
__device__ float g_xz   [(size_t)BB*LL*256];     // in_proj output (xi | z), channel-last
__device__ float g_xc   [(size_t)BB*LL*DD];      // conv+silu output, channel-last
__device__ float g_proj [(size_t)BB*LL*24];      // x_dbl: per pos, [k*6 + c]
__device__ float g_y0   [(size_t)BB*LL*DD];      // dir0 y + Ds*xc
__device__ float g_y1   [(size_t)BB*LL*DD];
__device__ float g_y2   [(size_t)BB*LL*DD];
__device__ float g_y3   [(size_t)BB*LL*DD];
__device__ float g_hend [(size_t)64*NSEG*DD];
__device__ float g_aprod[(size_t)64*NSEG*DD];
__device__ float g_init [(size_t)64*NSEG*DD];

// ---------------- math helpers (MUFU) ----------------
__device__ __forceinline__ float ex2f(float x){ float y; asm("ex2.approx.ftz.f32 %0,%1;" : "=f"(y) : "f"(x)); return y; }
__device__ __forceinline__ float lg2f(float x){ float y; asm("lg2.approx.ftz.f32 %0,%1;" : "=f"(y) : "f"(x)); return y; }
__device__ __forceinline__ float rcpf(float x){ float y; asm("rcp.approx.ftz.f32 %0,%1;" : "=f"(y) : "f"(x)); return y; }
__device__ __forceinline__ float fsigmoid(float x){ return rcpf(1.f + ex2f(-x*LOG2E)); }

// softplus in log2 domain: returns u = softplus(x)*log2e
__device__ __forceinline__ float sp_u(float x){
    float tt = ex2f(fminf(x, 20.f) * LOG2E);
    return (x > 20.f) ? x * LOG2E : lg2f(1.f + tt);
}

// position for scan step: pair0 row-major, pair1 column-major
__device__ __forceinline__ int scan_pos(int pair, int s, int i){
    return (pair == 0) ? ((s>>1)*WW + (s&1)*SEGLEN + i)
                       : (((s&1)*SEGLEN + i)*WW + (s>>1));
}

// ---------------- K0: zero d_out ----------------
__global__ void k_zero(float* out){
    int i = blockIdx.x*blockDim.x + threadIdx.x;
    if (i < BB*DD) out[i] = 0.f;
}

// ---------------- tensor-core GEMM helpers ----------------
__device__ __forceinline__ void ldsm4(uint32_t* r, uint32_t addr){
    asm volatile("ldmatrix.sync.aligned.m8n8.x4.shared.b16 {%0,%1,%2,%3}, [%4];"
        : "=r"(r[0]),"=r"(r[1]),"=r"(r[2]),"=r"(r[3]) : "r"(addr));
}
__device__ __forceinline__ void mma16816(float* c, const uint32_t* a, const uint32_t* b){
    asm volatile("mma.sync.aligned.m16n8k16.row.col.f32.bf16.bf16.f32 "
        "{%0,%1,%2,%3}, {%4,%5,%6,%7}, {%8,%9}, {%0,%1,%2,%3};"
        : "+f"(c[0]),"+f"(c[1]),"+f"(c[2]),"+f"(c[3])
        : "r"(a[0]),"r"(a[1]),"r"(a[2]),"r"(a[3]), "r"(b[0]),"r"(b[1]));
}
__device__ __forceinline__ uint32_t pkbf(__nv_bfloat162 h){ return *reinterpret_cast<uint32_t*>(&h); }

// ---------------- K1: in_proj GEMM (M=50176,N=256,K=128) bf16 split-precision MMA -------
__global__ void __launch_bounds__(256) k_gemm(const float* __restrict__ X, const float* __restrict__ Wm){
    __shared__ __align__(16) __nv_bfloat16 sA[2][128][40];
    __shared__ uint32_t sB[2][64][18];
    const int t = threadIdx.x;
    const int row0 = blockIdx.x * 128;
    const int col0 = blockIdx.y * 64;
    const int wid = t >> 5, lane = t & 31;
    const int mw = wid & 3, nw = wid >> 2;
    float acc[2][4][4] = {};

    for (int kb = 0; kb < 128; kb += 32){
        #pragma unroll
        for (int j = 0; j < 4; j++){
            int fid = t + j*256;
            int r = fid >> 3, kq = (fid & 7) << 2;
            float4 v = *(const float4*)&X[(size_t)(row0+r)*128 + kb + kq];
            __nv_bfloat162 h01 = __floats2bfloat162_rn(v.x, v.y);
            __nv_bfloat162 h23 = __floats2bfloat162_rn(v.z, v.w);
            float2 f01 = __bfloat1622float2(h01);
            float2 f23 = __bfloat1622float2(h23);
            *(__nv_bfloat162*)&sA[0][r][kq]   = h01;
            *(__nv_bfloat162*)&sA[0][r][kq+2] = h23;
            *(__nv_bfloat162*)&sA[1][r][kq]   = __floats2bfloat162_rn(v.x - f01.x, v.y - f01.y);
            *(__nv_bfloat162*)&sA[1][r][kq+2] = __floats2bfloat162_rn(v.z - f23.x, v.w - f23.y);
        }
        #pragma unroll
        for (int j = 0; j < 2; j++){
            int fid = t + j*256;
            int r = fid >> 3, kq = (fid & 7) << 2;
            float4 v = *(const float4*)&Wm[(size_t)(col0+r)*128 + kb + kq];
            __nv_bfloat162 h01 = __floats2bfloat162_rn(v.x, v.y);
            __nv_bfloat162 h23 = __floats2bfloat162_rn(v.z, v.w);
            float2 f01 = __bfloat1622float2(h01);
            float2 f23 = __bfloat1622float2(h23);
            sB[0][r][(kq>>1)  ] = pkbf(h01);
            sB[0][r][(kq>>1)+1] = pkbf(h23);
            sB[1][r][(kq>>1)  ] = pkbf(__floats2bfloat162_rn(v.x - f01.x, v.y - f01.y));
            sB[1][r][(kq>>1)+1] = pkbf(__floats2bfloat162_rn(v.z - f23.x, v.w - f23.y));
        }
        __syncthreads();
        #pragma unroll
        for (int ks = 0; ks < 2; ks++){
            uint32_t ah[2][4], al[2][4];
            #pragma unroll
            for (int f = 0; f < 2; f++){
                int rr = mw*32 + f*16 + (lane & 15);
                int cc = ks*16 + (lane >> 4)*8;
                ldsm4(ah[f], (uint32_t)__cvta_generic_to_shared(&sA[0][rr][cc]));
                ldsm4(al[f], (uint32_t)__cvta_generic_to_shared(&sA[1][rr][cc]));
            }
            #pragma unroll
            for (int j = 0; j < 4; j++){
                int nr = nw*32 + j*8 + (lane >> 2);
                int kp = ks*8 + (lane & 3);
                uint32_t bh[2] = { sB[0][nr][kp], sB[0][nr][kp+4] };
                uint32_t bl[2] = { sB[1][nr][kp], sB[1][nr][kp+4] };
                #pragma unroll
                for (int f = 0; f < 2; f++){
                    mma16816(acc[f][j], ah[f], bh);
                    mma16816(acc[f][j], ah[f], bl);
                    mma16816(acc[f][j], al[f], bh);
                }
            }
        }
        __syncthreads();
    }
    #pragma unroll
    for (int f = 0; f < 2; f++){
        #pragma unroll
        for (int j = 0; j < 4; j++){
            int r = row0 + mw*32 + f*16 + (lane >> 2);
            int c = col0 + nw*32 + j*8 + (lane & 3)*2;
            *(float2*)&g_xz[(size_t)r*256 + c]     = make_float2(acc[f][j][0], acc[f][j][1]);
            *(float2*)&g_xz[(size_t)(r+8)*256 + c] = make_float2(acc[f][j][2], acc[f][j][3]);
        }
    }
}

// ---------------- K2: depthwise conv + SiLU + fused x_dbl (warp-per-position) -------------
__global__ void __launch_bounds__(256) k_convp(const float* __restrict__ cw, const float* __restrict__ cb,
                                               const float* __restrict__ xpw){
    __shared__ float wsh[9][128];
    __shared__ float bsh[128];
    __shared__ float wp[24][132];
    __shared__ float red[8][32][25];
    const int t = threadIdx.x;
    for (int i = t; i < 1152; i += 256) wsh[i % 9][i / 9] = cw[i];
    if (t < 128) bsh[t] = cb[t];
    for (int i = t; i < 24*128; i += 256) wp[i>>7][i&127] = xpw[i];
    __syncthreads();

    const int lane = t & 31;
    const int warpid = t >> 5;
    const int dq = lane;
    int pos = blockIdx.x*8 + warpid;
    int rest = pos;
    int w = rest % WW; rest /= WW;
    int h = rest % HH;
    int b = rest / HH;

    float4 s = *(const float4*)&bsh[dq*4];
    #pragma unroll
    for (int dy = -1; dy <= 1; dy++){
        int hh = h + dy;
        bool okh = (hh >= 0) && (hh < HH);
        #pragma unroll
        for (int dx = -1; dx <= 1; dx++){
            int ww = w + dx;
            if (okh && ww >= 0 && ww < WW){
                float4 xv = *(const float4*)&g_xz[((size_t)(b*LL + hh*WW + ww))*256 + dq*4];
                float4 wt = *(const float4*)&wsh[(dy+1)*3 + (dx+1)][dq*4];
                s.x = fmaf(xv.x, wt.x, s.x);
                s.y = fmaf(xv.y, wt.y, s.y);
                s.z = fmaf(xv.z, wt.z, s.z);
                s.w = fmaf(xv.w, wt.w, s.w);
            }
        }
    }
    s.x *= fsigmoid(s.x); s.y *= fsigmoid(s.y); s.z *= fsigmoid(s.z); s.w *= fsigmoid(s.w);
    *(float4*)&g_xc[(size_t)pos*128 + dq*4] = s;

    #pragma unroll
    for (int c = 0; c < 24; c++){
        float4 wv = *(const float4*)&wp[c][dq*4];
        red[warpid][lane][c] = s.x*wv.x + s.y*wv.y + s.z*wv.z + s.w*wv.w;
    }
    __syncwarp();
    if (lane < 24){
        float outv = 0.f;
        #pragma unroll 8
        for (int i = 0; i < 32; i++) outv += red[warpid][i][lane];
        g_proj[(size_t)pos*24 + lane] = outv;
    }
}

// ---------------- K3: scan pass 1 — smem-staged proj, paired dirs ----------------
__global__ void __launch_bounds__(128) k_pass1(const float* __restrict__ dtw, const float* __restrict__ dtb,
                                               const float* __restrict__ alog){
    __shared__ __align__(16) float sproj[SEGLEN][12];
    const int s = blockIdx.x, b = blockIdx.y, pair = blockIdx.z;
    const int d = threadIdx.x;
    for (int j = d; j < SEGLEN*12; j += 128){
        int i = j / 12, c = j - i*12;
        sproj[i][c] = g_proj[(size_t)(b*LL + scan_pos(pair, s, i))*24 + pair*12 + c];
    }
    const int kf = pair*2, kb_ = pair*2 + 1;
    float4 wf = *(const float4*)&dtw[(size_t)(kf*128 + d)*4];
    float4 wb = *(const float4*)&dtw[(size_t)(kb_*128 + d)*4];
    float bf = dtb[kf*128 + d], bbs = dtb[kb_*128 + d];
    float Af = -ex2f(alog[kf*128 + d] * LOG2E);
    float Ab = -ex2f(alog[kb_*128 + d] * LOG2E);
    __syncthreads();

    float hf = 0.f, Pf = 1.f;
    float hb = 0.f, Pb = 1.f;
    #pragma unroll 4
    for (int i = 0; i < SEGLEN; i++){
        int bp = b*LL + scan_pos(pair, s, i);
        float xcv = g_xc[(size_t)bp*128 + d];
        float4 f0 = *(const float4*)&sproj[i][0];   // p0f p1f p2f p3f
        float4 f1 = *(const float4*)&sproj[i][4];   // Bf  Cf  p0b p1b
        float4 f2 = *(const float4*)&sproj[i][8];   // p2b p3b Bb  Cb
        // forward
        float xf = fmaf(wf.x, f0.x, bf);
        xf = fmaf(wf.y, f0.y, xf);
        xf = fmaf(wf.z, f0.z, xf);
        xf = fmaf(wf.w, f0.w, xf);
        float uf = sp_u(xf);
        float daf = ex2f(Af * uf);
        float dbf = uf * LN2 * f1.x * xcv;
        hf = fmaf(daf, hf, dbf);
        Pf *= daf;
        // backward (summary in forward order)
        float xb = fmaf(wb.x, f1.z, bbs);
        xb = fmaf(wb.y, f1.w, xb);
        xb = fmaf(wb.z, f2.x, xb);
        xb = fmaf(wb.w, f2.y, xb);
        float ub = sp_u(xb);
        float dab = ex2f(Ab * ub);
        float dbb = ub * LN2 * f2.z * xcv;
        hb = fmaf(dbb, Pb, hb);
        Pb *= dab;
    }
    const int gf = b*4 + kf, gb = b*4 + kb_;
    size_t if_ = ((size_t)gf*NSEG + s)*128 + d;
    size_t ib_ = ((size_t)gb*NSEG + (NSEG-1-s))*128 + d;
    g_hend[if_]  = hf;  g_aprod[if_] = Pf;
    g_hend[ib_]  = hb;  g_aprod[ib_] = Pb;
}

// ---------------- K4: combine (prefix over segments, per scan-chain) ----------------
__global__ void k_comb(){
    const int g = blockIdx.x, d = threadIdx.x;
    float carry = 0.f;
    #pragma unroll 8
    for (int s = 0; s < NSEG; s++){
        size_t idx = ((size_t)g*NSEG + s)*128 + d;
        g_init[idx] = carry;
        carry = fmaf(g_aprod[idx], carry, g_hend[idx]);
    }
}

// ---------------- K5: scan pass 2 — one block per direction, direct y write ----------
// sproj rows padded to 8 floats (32B) so float4 reads are aligned.
__global__ void __launch_bounds__(128) k_pass2(const float* __restrict__ dtw, const float* __restrict__ dtb,
                                               const float* __restrict__ alog, const float* __restrict__ Ds){
    __shared__ __align__(16) float sproj[SEGLEN][8];
    const int s = blockIdx.x, b = blockIdx.y, k = blockIdx.z;  // k = direction 0..3
    const int pair = k >> 1;
    const int bwd  = k & 1;
    const int d = threadIdx.x;
    for (int j = d; j < SEGLEN*6; j += 128){
        int i = j / 6, c = j - i*6;
        sproj[i][c] = g_proj[(size_t)(b*LL + scan_pos(pair, s, i))*24 + k*6 + c];
    }
    float4 wv = *(const float4*)&dtw[(size_t)(k*128 + d)*4];
    float bias = dtb[k*128 + d];
    float Av = -ex2f(alog[k*128 + d] * LOG2E);
    float sumDs = (k == 0) ? (Ds[d] + Ds[128+d] + Ds[256+d] + Ds[384+d]) : 0.f;
    float* yout = (k == 0) ? g_y0 : (k == 1) ? g_y1 : (k == 2) ? g_y2 : g_y3;
    __syncthreads();

    const int sseg = bwd ? (NSEG-1-s) : s;
    float hst = g_init[((size_t)(b*4 + k)*NSEG + sseg)*128 + d];
    const int i0   = bwd ? (SEGLEN-1) : 0;
    const int istp = bwd ? -1 : 1;
    #pragma unroll 4
    for (int n = 0; n < SEGLEN; n++){
        int i = i0 + n*istp;
        int bp = b*LL + scan_pos(pair, s, i);
        float xcv = g_xc[(size_t)bp*128 + d];
        float4 f0 = *(const float4*)&sproj[i][0];   // p0 p1 p2 p3  (32B row, aligned)
        float2 f1 = *(const float2*)&sproj[i][4];   // B C          (8B-aligned)
        float xdt = fmaf(wv.x, f0.x, bias);
        xdt = fmaf(wv.y, f0.y, xdt);
        xdt = fmaf(wv.z, f0.z, xdt);
        xdt = fmaf(wv.w, f0.w, xdt);
        float u  = sp_u(xdt);
        float da = ex2f(Av * u);
        float db = u * LN2 * f1.x * xcv;
        hst = fmaf(da, hst, db);
        float val = hst * f1.y;
        if (k == 0) val = fmaf(xcv, sumDs, val);
        yout[(size_t)bp*128 + d] = val;
    }
}

// ---------------- K6: LayerNorm + SiLU gate + spatial mean ----------------
__global__ void __launch_bounds__(256) k_final(const float* __restrict__ nw, const float* __restrict__ nb,
                                               float* __restrict__ out){
    const int b = blockIdx.y;
    const int t = threadIdx.x;
    const int warp = t >> 5, lane = t & 31;
    const int d4 = lane*4;
    float4 w4 = *(const float4*)&nw[d4];
    float4 b4 = *(const float4*)&nb[d4];

    float4 acc = make_float4(0.f,0.f,0.f,0.f);
    #pragma unroll 2
    for (int j = 0; j < 8; j++){
        int p = blockIdx.x*64 + warp*8 + j;
        size_t base = ((size_t)(b*LL + p))*128 + d4;
        float4 v  = *(const float4*)&g_y0[base];
        float4 v1 = *(const float4*)&g_y1[base];
        float4 v2 = *(const float4*)&g_y2[base];
        float4 v3 = *(const float4*)&g_y3[base];
        v.x += v1.x + v2.x + v3.x;
        v.y += v1.y + v2.y + v3.y;
        v.z += v1.z + v2.z + v3.z;
        v.w += v1.w + v2.w + v3.w;
        float sm = v.x+v.y+v.z+v.w;
        #pragma unroll
        for (int o = 16; o > 0; o >>= 1) sm += __shfl_xor_sync(~0u, sm, o);
        float mu = sm * (1.f/128.f);
        float4 dv = make_float4(v.x-mu, v.y-mu, v.z-mu, v.w-mu);
        float s2 = dv.x*dv.x + dv.y*dv.y + dv.z*dv.z + dv.w*dv.w;
        #pragma unroll
        for (int o = 16; o > 0; o >>= 1) s2 += __shfl_xor_sync(~0u, s2, o);
        float rstd = rsqrtf(s2 * (1.f/128.f) + 1e-5f);
        float4 z = *(const float4*)&g_xz[((size_t)(b*LL + p))*256 + 128 + d4];
        float gx = z.x*fsigmoid(z.x), gy = z.y*fsigmoid(z.y);
        float gz = z.z*fsigmoid(z.z), gw = z.w*fsigmoid(z.w);
        acc.x = fmaf(fmaf(dv.x*rstd, w4.x, b4.x), gx, acc.x);
        acc.y = fmaf(fmaf(dv.y*rstd, w4.y, b4.y), gy, acc.y);
        acc.z = fmaf(fmaf(dv.z*rstd, w4.z, b4.z), gz, acc.z);
        acc.w = fmaf(fmaf(dv.w*rstd, w4.w, b4.w), gw, acc.w);
    }
    const float sc = 1.f/(float)LL;
    atomicAdd(&out[b*128 + d4 + 0], acc.x*sc);
    atomicAdd(&out[b*128 + d4 + 1], acc.y*sc);
    atomicAdd(&out[b*128 + d4 + 2], acc.z*sc);
    atomicAdd(&out[b*128 + d4 + 3], acc.w*sc);
}

// ---------------- launch ----------------
extern "C" void kernel_launch(void* const* d_in, const int* in_sizes, int n_in,
                              void* d_out, int out_size){
    const float* x    = (const float*)d_in[0];
    const float* inw  = (const float*)d_in[1];
    const float* cw   = (const float*)d_in[2];
    const float* cb   = (const float*)d_in[3];
    const float* xpw  = (const float*)d_in[4];
    const float* dtw  = (const float*)d_in[5];
    const float* dtb  = (const float*)d_in[6];
    const float* alog = (const float*)d_in[7];
    const float* Ds   = (const float*)d_in[8];
    const float* onw  = (const float*)d_in[9];
    const float* onb  = (const float*)d_in[10];
    float* out = (float*)d_out;

    k_zero<<<(BB*DD + 255)/256, 256>>>(out);
    k_gemm<<<dim3((BB*LL)/128, 4), 256>>>(x, inw);
    k_convp<<<(BB*LL)/8, 256>>>(cw, cb, xpw);
    k_pass1<<<dim3(NSEG, BB, 2), 128>>>(dtw, dtb, alog);
    k_comb<<<64, 128>>>();
    k_pass2<<<dim3(NSEG, BB, 4), 128>>>(dtw, dtb, alog, Ds);
    k_final<<<dim3(LL/64, BB), 256>>>(onw, onb, out);
}

// round 10
// speedup vs baseline: 1.1361x; 1.1361x over previous
#include <cuda_runtime.h>
#include <cuda_bf16.h>
#include <cstdint>

// ---------------- problem constants ----------------
#define BB 16
#define HH 56
#define WW 56
#define LL (HH*WW)      // 3136
#define DD 128
#define KK 4
#define NSEG 112
#define SEGLEN 28       // 112*28 = 3136

#define LOG2E 1.4426950408889634f
#define LN2   0.6931471805599453f

// ---------------- scratch (device globals; no allocs allowed) ----------------
__device__ float g_xz   [(size_t)BB*LL*256];     // in_proj output (xi | z), channel-last
__device__ float g_xc   [(size_t)BB*LL*DD];      // conv+silu output, channel-last
__device__ float g_proj [(size_t)BB*LL*24];      // x_dbl: per pos, [k*6 + c]
__device__ float g_ysum [(size_t)BB*LL*DD];      // pair01 y + Ds*xc
__device__ float g_ysum2[(size_t)BB*LL*DD];      // pair23 y
__device__ float g_hend [(size_t)64*NSEG*DD];
__device__ float g_aprod[(size_t)64*NSEG*DD];
__device__ float g_init [(size_t)64*NSEG*DD];

// ---------------- math helpers (MUFU) ----------------
__device__ __forceinline__ float ex2f(float x){ float y; asm("ex2.approx.ftz.f32 %0,%1;" : "=f"(y) : "f"(x)); return y; }
__device__ __forceinline__ float lg2f(float x){ float y; asm("lg2.approx.ftz.f32 %0,%1;" : "=f"(y) : "f"(x)); return y; }
__device__ __forceinline__ float rcpf(float x){ float y; asm("rcp.approx.ftz.f32 %0,%1;" : "=f"(y) : "f"(x)); return y; }
__device__ __forceinline__ float fsigmoid(float x){ return rcpf(1.f + ex2f(-x*LOG2E)); }

// softplus in log2 domain: returns u = softplus(x)*log2e
__device__ __forceinline__ float sp_u(float x){
    float tt = ex2f(fminf(x, 20.f) * LOG2E);
    return (x > 20.f) ? x * LOG2E : lg2f(1.f + tt);
}

// position for scan step: pair0 row-major, pair1 column-major
__device__ __forceinline__ int scan_pos(int pair, int s, int i){
    return (pair == 0) ? ((s>>1)*WW + (s&1)*SEGLEN + i)
                       : (((s&1)*SEGLEN + i)*WW + (s>>1));
}

// ---------------- K0: zero d_out ----------------
__global__ void k_zero(float* out){
    int i = blockIdx.x*blockDim.x + threadIdx.x;
    if (i < BB*DD) out[i] = 0.f;
}

// ---------------- tensor-core GEMM helpers ----------------
__device__ __forceinline__ void ldsm4(uint32_t* r, uint32_t addr){
    asm volatile("ldmatrix.sync.aligned.m8n8.x4.shared.b16 {%0,%1,%2,%3}, [%4];"
        : "=r"(r[0]),"=r"(r[1]),"=r"(r[2]),"=r"(r[3]) : "r"(addr));
}
__device__ __forceinline__ void mma16816(float* c, const uint32_t* a, const uint32_t* b){
    asm volatile("mma.sync.aligned.m16n8k16.row.col.f32.bf16.bf16.f32 "
        "{%0,%1,%2,%3}, {%4,%5,%6,%7}, {%8,%9}, {%0,%1,%2,%3};"
        : "+f"(c[0]),"+f"(c[1]),"+f"(c[2]),"+f"(c[3])
        : "r"(a[0]),"r"(a[1]),"r"(a[2]),"r"(a[3]), "r"(b[0]),"r"(b[1]));
}
__device__ __forceinline__ uint32_t pkbf(__nv_bfloat162 h){ return *reinterpret_cast<uint32_t*>(&h); }

// ---------------- K1: in_proj GEMM (M=50176,N=256,K=128) bf16 split-precision MMA -------
__global__ void __launch_bounds__(256) k_gemm(const float* __restrict__ X, const float* __restrict__ Wm){
    __shared__ __align__(16) __nv_bfloat16 sA[2][128][40];
    __shared__ uint32_t sB[2][64][18];
    const int t = threadIdx.x;
    const int row0 = blockIdx.x * 128;
    const int col0 = blockIdx.y * 64;
    const int wid = t >> 5, lane = t & 31;
    const int mw = wid & 3, nw = wid >> 2;
    float acc[2][4][4] = {};

    for (int kb = 0; kb < 128; kb += 32){
        #pragma unroll
        for (int j = 0; j < 4; j++){
            int fid = t + j*256;
            int r = fid >> 3, kq = (fid & 7) << 2;
            float4 v = *(const float4*)&X[(size_t)(row0+r)*128 + kb + kq];
            __nv_bfloat162 h01 = __floats2bfloat162_rn(v.x, v.y);
            __nv_bfloat162 h23 = __floats2bfloat162_rn(v.z, v.w);
            float2 f01 = __bfloat1622float2(h01);
            float2 f23 = __bfloat1622float2(h23);
            *(__nv_bfloat162*)&sA[0][r][kq]   = h01;
            *(__nv_bfloat162*)&sA[0][r][kq+2] = h23;
            *(__nv_bfloat162*)&sA[1][r][kq]   = __floats2bfloat162_rn(v.x - f01.x, v.y - f01.y);
            *(__nv_bfloat162*)&sA[1][r][kq+2] = __floats2bfloat162_rn(v.z - f23.x, v.w - f23.y);
        }
        #pragma unroll
        for (int j = 0; j < 2; j++){
            int fid = t + j*256;
            int r = fid >> 3, kq = (fid & 7) << 2;
            float4 v = *(const float4*)&Wm[(size_t)(col0+r)*128 + kb + kq];
            __nv_bfloat162 h01 = __floats2bfloat162_rn(v.x, v.y);
            __nv_bfloat162 h23 = __floats2bfloat162_rn(v.z, v.w);
            float2 f01 = __bfloat1622float2(h01);
            float2 f23 = __bfloat1622float2(h23);
            sB[0][r][(kq>>1)  ] = pkbf(h01);
            sB[0][r][(kq>>1)+1] = pkbf(h23);
            sB[1][r][(kq>>1)  ] = pkbf(__floats2bfloat162_rn(v.x - f01.x, v.y - f01.y));
            sB[1][r][(kq>>1)+1] = pkbf(__floats2bfloat162_rn(v.z - f23.x, v.w - f23.y));
        }
        __syncthreads();
        #pragma unroll
        for (int ks = 0; ks < 2; ks++){
            uint32_t ah[2][4], al[2][4];
            #pragma unroll
            for (int f = 0; f < 2; f++){
                int rr = mw*32 + f*16 + (lane & 15);
                int cc = ks*16 + (lane >> 4)*8;
                ldsm4(ah[f], (uint32_t)__cvta_generic_to_shared(&sA[0][rr][cc]));
                ldsm4(al[f], (uint32_t)__cvta_generic_to_shared(&sA[1][rr][cc]));
            }
            #pragma unroll
            for (int j = 0; j < 4; j++){
                int nr = nw*32 + j*8 + (lane >> 2);
                int kp = ks*8 + (lane & 3);
                uint32_t bh[2] = { sB[0][nr][kp], sB[0][nr][kp+4] };
                uint32_t bl[2] = { sB[1][nr][kp], sB[1][nr][kp+4] };
                #pragma unroll
                for (int f = 0; f < 2; f++){
                    mma16816(acc[f][j], ah[f], bh);
                    mma16816(acc[f][j], ah[f], bl);
                    mma16816(acc[f][j], al[f], bh);
                }
            }
        }
        __syncthreads();
    }
    #pragma unroll
    for (int f = 0; f < 2; f++){
        #pragma unroll
        for (int j = 0; j < 4; j++){
            int r = row0 + mw*32 + f*16 + (lane >> 2);
            int c = col0 + nw*32 + j*8 + (lane & 3)*2;
            *(float2*)&g_xz[(size_t)r*256 + c]     = make_float2(acc[f][j][0], acc[f][j][1]);
            *(float2*)&g_xz[(size_t)(r+8)*256 + c] = make_float2(acc[f][j][2], acc[f][j][3]);
        }
    }
}

// ---------------- K2: sliding-window depthwise conv + SiLU + fused x_dbl -----------------
// warp = (b, h, 14-wide chunk); lane = channel quad; 3x3 window kept in registers.
__global__ void __launch_bounds__(256) k_convp(const float* __restrict__ cw, const float* __restrict__ cb,
                                               const float* __restrict__ xpw){
    __shared__ float wsh[9][128];
    __shared__ float bsh[128];
    __shared__ float wp[24][132];
    __shared__ float red[8][32][25];
    const int t = threadIdx.x;
    for (int i = t; i < 1152; i += 256) wsh[i % 9][i / 9] = cw[i];
    if (t < 128) bsh[t] = cb[t];
    for (int i = t; i < 24*128; i += 256) wp[i>>7][i&127] = xpw[i];
    __syncthreads();

    const int lane = t & 31;
    const int warpid = t >> 5;
    const int dq4 = lane*4;
    int gw = blockIdx.x*8 + warpid;          // 3584 warps total
    const int ch = gw & 3; gw >>= 2;
    const int h  = gw % HH;
    const int b  = gw / HH;
    const int hm = (h > 0)    ? h-1 : 0;     // clamped (weight zeroed when invalid)
    const int hp = (h < HH-1) ? h+1 : HH-1;

    // weights in registers with row-validity folded in
    float4 wreg[9];
    #pragma unroll
    for (int tap = 0; tap < 9; tap++){
        int dy = tap/3 - 1;
        int hh = h + dy;
        float4 wv = *(const float4*)&wsh[tap][dq4];
        bool ok = (hh >= 0) && (hh < HH);
        wreg[tap] = ok ? wv : make_float4(0.f,0.f,0.f,0.f);
    }
    float4 bias = *(const float4*)&bsh[dq4];

    const size_t rm = ((size_t)(b*LL + hm*WW))*256 + dq4;
    const size_t r0 = ((size_t)(b*LL + h *WW))*256 + dq4;
    const size_t rp = ((size_t)(b*LL + hp*WW))*256 + dq4;

    float4 cA[3], cB[3], cC[3];
    const float4 z4 = make_float4(0.f,0.f,0.f,0.f);
    const int w0 = ch*14;
    // init window columns w0-1 and w0
    if (w0 > 0){
        cA[0] = *(const float4*)&g_xz[rm + (size_t)(w0-1)*256];
        cA[1] = *(const float4*)&g_xz[r0 + (size_t)(w0-1)*256];
        cA[2] = *(const float4*)&g_xz[rp + (size_t)(w0-1)*256];
    } else { cA[0]=cA[1]=cA[2]=z4; }
    cB[0] = *(const float4*)&g_xz[rm + (size_t)w0*256];
    cB[1] = *(const float4*)&g_xz[r0 + (size_t)w0*256];
    cB[2] = *(const float4*)&g_xz[rp + (size_t)w0*256];

    for (int w = w0; w < w0+14; w++){
        if (w+1 < WW){
            cC[0] = *(const float4*)&g_xz[rm + (size_t)(w+1)*256];
            cC[1] = *(const float4*)&g_xz[r0 + (size_t)(w+1)*256];
            cC[2] = *(const float4*)&g_xz[rp + (size_t)(w+1)*256];
        } else { cC[0]=cC[1]=cC[2]=z4; }

        float4 s = bias;
        #pragma unroll
        for (int r = 0; r < 3; r++){
            float4 wa = wreg[r*3+0], wb = wreg[r*3+1], wc = wreg[r*3+2];
            s.x = fmaf(cA[r].x, wa.x, s.x); s.y = fmaf(cA[r].y, wa.y, s.y);
            s.z = fmaf(cA[r].z, wa.z, s.z); s.w = fmaf(cA[r].w, wa.w, s.w);
            s.x = fmaf(cB[r].x, wb.x, s.x); s.y = fmaf(cB[r].y, wb.y, s.y);
            s.z = fmaf(cB[r].z, wb.z, s.z); s.w = fmaf(cB[r].w, wb.w, s.w);
            s.x = fmaf(cC[r].x, wc.x, s.x); s.y = fmaf(cC[r].y, wc.y, s.y);
            s.z = fmaf(cC[r].z, wc.z, s.z); s.w = fmaf(cC[r].w, wc.w, s.w);
        }
        s.x *= fsigmoid(s.x); s.y *= fsigmoid(s.y);
        s.z *= fsigmoid(s.z); s.w *= fsigmoid(s.w);
        int pos = b*LL + h*WW + w;
        *(float4*)&g_xc[(size_t)pos*128 + dq4] = s;

        // fused x_dbl: per-lane partials, smem transpose reduce
        #pragma unroll
        for (int c = 0; c < 24; c++){
            float4 wv = *(const float4*)&wp[c][dq4];
            red[warpid][lane][c] = s.x*wv.x + s.y*wv.y + s.z*wv.z + s.w*wv.w;
        }
        __syncwarp();
        if (lane < 24){
            float outv = 0.f;
            #pragma unroll 8
            for (int i = 0; i < 32; i++) outv += red[warpid][i][lane];
            g_proj[(size_t)pos*24 + lane] = outv;
        }
        __syncwarp();
        cA[0]=cB[0]; cA[1]=cB[1]; cA[2]=cB[2];
        cB[0]=cC[0]; cB[1]=cC[1]; cB[2]=cC[2];
    }
}

// ---------------- K3: scan pass 1 — smem-staged proj, paired dirs ----------------
__global__ void __launch_bounds__(128) k_pass1(const float* __restrict__ dtw, const float* __restrict__ dtb,
                                               const float* __restrict__ alog){
    __shared__ __align__(16) float sproj[SEGLEN][12];
    const int s = blockIdx.x, b = blockIdx.y, pair = blockIdx.z;
    const int d = threadIdx.x;
    for (int j = d; j < SEGLEN*12; j += 128){
        int i = j / 12, c = j - i*12;
        sproj[i][c] = g_proj[(size_t)(b*LL + scan_pos(pair, s, i))*24 + pair*12 + c];
    }
    const int kf = pair*2, kb_ = pair*2 + 1;
    float4 wf = *(const float4*)&dtw[(size_t)(kf*128 + d)*4];
    float4 wb = *(const float4*)&dtw[(size_t)(kb_*128 + d)*4];
    float bf = dtb[kf*128 + d], bbs = dtb[kb_*128 + d];
    float Af = -ex2f(alog[kf*128 + d] * LOG2E);
    float Ab = -ex2f(alog[kb_*128 + d] * LOG2E);
    __syncthreads();

    float hf = 0.f, Pf = 1.f;
    float hb = 0.f, Pb = 1.f;
    #pragma unroll 4
    for (int i = 0; i < SEGLEN; i++){
        int bp = b*LL + scan_pos(pair, s, i);
        float xcv = g_xc[(size_t)bp*128 + d];
        float4 f0 = *(const float4*)&sproj[i][0];   // p0f p1f p2f p3f
        float4 f1 = *(const float4*)&sproj[i][4];   // Bf  Cf  p0b p1b
        float4 f2 = *(const float4*)&sproj[i][8];   // p2b p3b Bb  Cb
        // forward
        float xf = fmaf(wf.x, f0.x, bf);
        xf = fmaf(wf.y, f0.y, xf);
        xf = fmaf(wf.z, f0.z, xf);
        xf = fmaf(wf.w, f0.w, xf);
        float uf = sp_u(xf);
        float daf = ex2f(Af * uf);
        float dbf = uf * LN2 * f1.x * xcv;
        hf = fmaf(daf, hf, dbf);
        Pf *= daf;
        // backward (summary in forward order)
        float xb = fmaf(wb.x, f1.z, bbs);
        xb = fmaf(wb.y, f1.w, xb);
        xb = fmaf(wb.z, f2.x, xb);
        xb = fmaf(wb.w, f2.y, xb);
        float ub = sp_u(xb);
        float dab = ex2f(Ab * ub);
        float dbb = ub * LN2 * f2.z * xcv;
        hb = fmaf(dbb, Pb, hb);
        Pb *= dab;
    }
    const int gf = b*4 + kf, gb = b*4 + kb_;
    size_t if_ = ((size_t)gf*NSEG + s)*128 + d;
    size_t ib_ = ((size_t)gb*NSEG + (NSEG-1-s))*128 + d;
    g_hend[if_]  = hf;  g_aprod[if_] = Pf;
    g_hend[ib_]  = hb;  g_aprod[ib_] = Pb;
}

// ---------------- K4: combine (prefix over segments, per scan-chain) ----------------
__global__ void k_comb(){
    const int g = blockIdx.x, d = threadIdx.x;
    float carry = 0.f;
    #pragma unroll 8
    for (int s = 0; s < NSEG; s++){
        size_t idx = ((size_t)g*NSEG + s)*128 + d;
        g_init[idx] = carry;
        carry = fmaf(g_aprod[idx], carry, g_hend[idx]);
    }
}

// ---------------- K5: scan pass 2 — smem-staged proj+xc, both pairs concurrent ----------
__global__ void __launch_bounds__(128) k_pass2(const float* __restrict__ dtw, const float* __restrict__ dtb,
                                               const float* __restrict__ alog, const float* __restrict__ Ds){
    __shared__ __align__(16) float sproj[SEGLEN][12];
    __shared__ float sxc [SEGLEN][128];
    __shared__ float ybuf[SEGLEN][128];
    const int s = blockIdx.x, b = blockIdx.y, pair = blockIdx.z;
    const int d = threadIdx.x;
    for (int j = d; j < SEGLEN*12; j += 128){
        int i = j / 12, c = j - i*12;
        sproj[i][c] = g_proj[(size_t)(b*LL + scan_pos(pair, s, i))*24 + pair*12 + c];
    }
    const int kf = pair*2, kb_ = pair*2 + 1;
    float4 wf = *(const float4*)&dtw[(size_t)(kf*128 + d)*4];
    float4 wb = *(const float4*)&dtw[(size_t)(kb_*128 + d)*4];
    float bf = dtb[kf*128 + d], bbs = dtb[kb_*128 + d];
    float Af = -ex2f(alog[kf*128 + d] * LOG2E);
    float Ab = -ex2f(alog[kb_*128 + d] * LOG2E);
    const int gf = b*4 + kf, gb = b*4 + kb_;
    __syncthreads();

    // backward direction: descending traversal; stash xc in smem
    float hb = g_init[((size_t)gb*NSEG + (NSEG-1-s))*128 + d];
    #pragma unroll 4
    for (int i = SEGLEN-1; i >= 0; i--){
        int bp = b*LL + scan_pos(pair, s, i);
        float xcv = g_xc[(size_t)bp*128 + d];
        sxc[i][d] = xcv;
        float4 f1 = *(const float4*)&sproj[i][4];   // Bf Cf p0b p1b
        float4 f2 = *(const float4*)&sproj[i][8];   // p2b p3b Bb Cb
        float xb = fmaf(wb.x, f1.z, bbs);
        xb = fmaf(wb.y, f1.w, xb);
        xb = fmaf(wb.z, f2.x, xb);
        xb = fmaf(wb.w, f2.y, xb);
        float ub = sp_u(xb);
        float dab = ex2f(Ab * ub);
        float dbb = ub * LN2 * f2.z * xcv;
        hb = fmaf(dab, hb, dbb);
        ybuf[i][d] = hb * f2.w;
    }
    // forward direction + merge (xc from smem, zero global loads)
    float sumDs = Ds[d] + Ds[128+d] + Ds[256+d] + Ds[384+d];
    float hf = g_init[((size_t)gf*NSEG + s)*128 + d];
    #pragma unroll 4
    for (int i = 0; i < SEGLEN; i++){
        int bp = b*LL + scan_pos(pair, s, i);
        float xcv = sxc[i][d];
        float4 f0 = *(const float4*)&sproj[i][0];   // p0f p1f p2f p3f
        float4 f1 = *(const float4*)&sproj[i][4];   // Bf Cf ..
        float xf = fmaf(wf.x, f0.x, bf);
        xf = fmaf(wf.y, f0.y, xf);
        xf = fmaf(wf.z, f0.z, xf);
        xf = fmaf(wf.w, f0.w, xf);
        float uf = sp_u(xf);
        float daf = ex2f(Af * uf);
        float dbf = uf * LN2 * f1.x * xcv;
        hf = fmaf(daf, hf, dbf);
        float val = fmaf(hf, f1.y, ybuf[i][d]);
        if (pair == 0){
            g_ysum[(size_t)bp*128 + d] = fmaf(xcv, sumDs, val);
        } else {
            g_ysum2[(size_t)bp*128 + d] = val;
        }
    }
}

// ---------------- K6: LayerNorm + SiLU gate + spatial mean ----------------
__global__ void __launch_bounds__(256) k_final(const float* __restrict__ nw, const float* __restrict__ nb,
                                               float* __restrict__ out){
    const int b = blockIdx.y;
    const int t = threadIdx.x;
    const int warp = t >> 5, lane = t & 31;
    const int d4 = lane*4;
    float4 w4 = *(const float4*)&nw[d4];
    float4 b4 = *(const float4*)&nb[d4];

    float4 acc = make_float4(0.f,0.f,0.f,0.f);
    #pragma unroll 2
    for (int j = 0; j < 8; j++){
        int p = blockIdx.x*64 + warp*8 + j;
        size_t base = ((size_t)(b*LL + p))*128 + d4;
        float4 v  = *(const float4*)&g_ysum[base];
        float4 v2 = *(const float4*)&g_ysum2[base];
        v.x += v2.x; v.y += v2.y; v.z += v2.z; v.w += v2.w;
        float sm = v.x+v.y+v.z+v.w;
        #pragma unroll
        for (int o = 16; o > 0; o >>= 1) sm += __shfl_xor_sync(~0u, sm, o);
        float mu = sm * (1.f/128.f);
        float4 dv = make_float4(v.x-mu, v.y-mu, v.z-mu, v.w-mu);
        float s2 = dv.x*dv.x + dv.y*dv.y + dv.z*dv.z + dv.w*dv.w;
        #pragma unroll
        for (int o = 16; o > 0; o >>= 1) s2 += __shfl_xor_sync(~0u, s2, o);
        float rstd = rsqrtf(s2 * (1.f/128.f) + 1e-5f);
        float4 z = *(const float4*)&g_xz[((size_t)(b*LL + p))*256 + 128 + d4];
        float gx = z.x*fsigmoid(z.x), gy = z.y*fsigmoid(z.y);
        float gz = z.z*fsigmoid(z.z), gw = z.w*fsigmoid(z.w);
        acc.x = fmaf(fmaf(dv.x*rstd, w4.x, b4.x), gx, acc.x);
        acc.y = fmaf(fmaf(dv.y*rstd, w4.y, b4.y), gy, acc.y);
        acc.z = fmaf(fmaf(dv.z*rstd, w4.z, b4.z), gz, acc.z);
        acc.w = fmaf(fmaf(dv.w*rstd, w4.w, b4.w), gw, acc.w);
    }
    const float sc = 1.f/(float)LL;
    atomicAdd(&out[b*128 + d4 + 0], acc.x*sc);
    atomicAdd(&out[b*128 + d4 + 1], acc.y*sc);
    atomicAdd(&out[b*128 + d4 + 2], acc.z*sc);
    atomicAdd(&out[b*128 + d4 + 3], acc.w*sc);
}

// ---------------- launch ----------------
extern "C" void kernel_launch(void* const* d_in, const int* in_sizes, int n_in,
                              void* d_out, int out_size){
    const float* x    = (const float*)d_in[0];
    const float* inw  = (const float*)d_in[1];
    const float* cw   = (const float*)d_in[2];
    const float* cb   = (const float*)d_in[3];
    const float* xpw  = (const float*)d_in[4];
    const float* dtw  = (const float*)d_in[5];
    const float* dtb  = (const float*)d_in[6];
    const float* alog = (const float*)d_in[7];
    const float* Ds   = (const float*)d_in[8];
    const float* onw  = (const float*)d_in[9];
    const float* onb  = (const float*)d_in[10];
    float* out = (float*)d_out;

    k_zero<<<(BB*DD + 255)/256, 256>>>(out);
    k_gemm<<<dim3((BB*LL)/128, 4), 256>>>(x, inw);
    k_convp<<<(BB*HH*4)/8, 256>>>(cw, cb, xpw);
    k_pass1<<<dim3(NSEG, BB, 2), 128>>>(dtw, dtb, alog);
    k_comb<<<64, 128>>>();
    k_pass2<<<dim3(NSEG, BB, 2), 128>>>(dtw, dtb, alog, Ds);
    k_final<<<dim3(LL/64, BB), 256>>>(onw, onb, out);
}